// round 11
// baseline (speedup 1.0000x reference)
#include <cuda_runtime.h>
#include <cuda_bf16.h>
#include <math.h>
#include <stdint.h>

#define BSZ   65536
#define ZN    512
#define GVN   768
#define XSTR  129
#define NPAIR 21
#define KSPLIT 16
#define KPC   (BSZ / KSPLIT)       // 4096
#define KC    64
#define GT    (KPC / KC)           // 64
#define TILE_BYTES (128 * KC * 2)  // 16384 bytes per operand tile
#define BUF_BYTES  (2 * TILE_BYTES)
#define GRAM_SMEM  (2 * BUF_BYTES) // 65536
#define LSTM_SMEM  83968

__device__ float g_Wp[256 * 512];
__device__ float g_bp[512];
__device__ float g_gv[(size_t)BSZ * GVN];
__device__ __nv_bfloat16 g_gvT[(size_t)GVN * BSZ];
__device__ float g_Gpart[(size_t)NPAIR * KSPLIT * 128 * 128];
__device__ float g_G[GVN * GVN];
__device__ float g_r[GVN];
__device__ float g_thA[GVN];
__device__ float g_thB[GVN];
__device__ int   g_maxidx;

__constant__ int c_pa[NPAIR] = {0,0,0,0,0,0,1,1,1,1,1,2,2,2,2,3,3,3,4,4,5};
__constant__ int c_pb[NPAIR] = {0,1,2,3,4,5,1,2,3,4,5,2,3,4,5,3,4,5,4,5,5};

__device__ __forceinline__ unsigned smem_u32(const void* p) {
    unsigned a;
    asm("{ .reg .u64 t; cvta.to.shared.u64 t, %1; cvt.u32.u64 %0, t; }" : "=r"(a) : "l"(p));
    return a;
}
__device__ __forceinline__ void cp_async16(unsigned dst, const void* src) {
    asm volatile("cp.async.cg.shared.global [%0], [%1], 16;\n" :: "r"(dst), "l"(src));
}
__device__ __forceinline__ void ldsm_x4(unsigned addr, unsigned& r0, unsigned& r1,
                                        unsigned& r2, unsigned& r3) {
    asm volatile("ldmatrix.sync.aligned.m8n8.x4.shared.b16 {%0,%1,%2,%3}, [%4];"
                 : "=r"(r0), "=r"(r1), "=r"(r2), "=r"(r3) : "r"(addr));
}
__device__ __forceinline__ void mma_bf16(float& c0, float& c1, float& c2, float& c3,
                                         unsigned a0, unsigned a1, unsigned a2, unsigned a3,
                                         unsigned b0, unsigned b1) {
    asm volatile(
        "mma.sync.aligned.m16n8k16.row.col.f32.bf16.bf16.f32 "
        "{%0,%1,%2,%3}, {%4,%5,%6,%7}, {%8,%9}, {%0,%1,%2,%3};"
        : "+f"(c0), "+f"(c1), "+f"(c2), "+f"(c3)
        : "r"(a0), "r"(a1), "r"(a2), "r"(a3), "r"(b0), "r"(b1));
}

__device__ __forceinline__ float sigmoidf_(float x) { return 1.0f / (1.0f + __expf(-x)); }
__device__ __forceinline__ float tanhf_(float x) {
    float t = __expf(-2.0f * fabsf(x));
    return copysignf((1.0f - t) / (1.0f + t), x);
}

__global__ void prep_kernel(const float* __restrict__ W_ih,
                            const float* __restrict__ W_hh,
                            const float* __restrict__ b_ih) {
    int t = blockIdx.x * blockDim.x + threadIdx.x;
    if (t < GVN) { g_r[t] = 0.0f; return; }
    t -= GVN;
    if (t < GVN) { g_thA[t] = 1.0f; return; }
    t -= GVN;
    if (t < ZN) { int j = t >> 2, g = t & 3; g_bp[t] = b_ih[g * 128 + j]; return; }
    t -= ZN;
    if (t < 256 * 512) {
        int k = t >> 9, cp = t & 511;
        int j = cp >> 2, g = cp & 3, wr = g * 128 + j;
        g_Wp[t] = (k < 128) ? W_ih[wr * 128 + k] : W_hh[wr * 128 + (k - 128)];
    }
}

// ---------------- kernel 1: z-GEMM + gates + bf16 transposed staging ----------------
__global__ __launch_bounds__(256) void lstm_kernel(
        const float* __restrict__ x, const float* __restrict__ h,
        const float* __restrict__ c, float* __restrict__ out) {
    extern __shared__ char smraw[];
    float* As  = (float*)(smraw);
    float* Bs  = (float*)(smraw + 16896);
    float* r_s = (float*)(smraw + 33280);
    __nv_bfloat16* sT6 = (__nv_bfloat16*)(smraw + 34048);  // [6][32][130]

    const int tid = threadIdx.x, ntile = blockIdx.x;
    const int row0 = blockIdx.y * 128, n0 = ntile * 128;
    const int kkL = tid & 31, m0 = tid >> 5;
    const int nL = tid & 127, kk0 = tid >> 7;
    const int ty = tid >> 4, tx = tid & 15;

    float acc[8][8];
#pragma unroll
    for (int i = 0; i < 8; ++i)
#pragma unroll
        for (int j = 0; j < 8; ++j) acc[i][j] = 0.0f;

    for (int kt = 0; kt < 8; ++kt) {
        const int k0 = kt * 32;
        const float* src; int stride, koff;
        if (k0 < 128) { src = x; stride = XSTR; koff = k0; }
        else          { src = h; stride = 128;  koff = k0 - 128; }
#pragma unroll
        for (int i = 0; i < 16; ++i) {
            int m = m0 + 8 * i;
            As[kkL * 132 + m] = src[(size_t)(row0 + m) * stride + koff + kkL];
        }
#pragma unroll
        for (int i = 0; i < 16; ++i) {
            int kk = kk0 + 2 * i;
            Bs[kk * 128 + nL] = g_Wp[(k0 + kk) * 512 + n0 + nL];
        }
        __syncthreads();
#pragma unroll
        for (int kk = 0; kk < 32; ++kk) {
            float4 a0 = *reinterpret_cast<const float4*>(&As[kk * 132 + ty * 8]);
            float4 a1 = *reinterpret_cast<const float4*>(&As[kk * 132 + ty * 8 + 4]);
            float4 b0 = *reinterpret_cast<const float4*>(&Bs[kk * 128 + tx * 8]);
            float4 b1 = *reinterpret_cast<const float4*>(&Bs[kk * 128 + tx * 8 + 4]);
            float av[8] = {a0.x, a0.y, a0.z, a0.w, a1.x, a1.y, a1.z, a1.w};
            float bv[8] = {b0.x, b0.y, b0.z, b0.w, b1.x, b1.y, b1.z, b1.w};
#pragma unroll
            for (int i = 0; i < 8; ++i)
#pragma unroll
                for (int j = 0; j < 8; ++j)
                    acc[i][j] = fmaf(av[i], bv[j], acc[i][j]);
        }
        __syncthreads();
    }

    if (tid < 192) r_s[tid] = 0.0f;
    __syncthreads();

    float bb[8];
#pragma unroll
    for (int cc = 0; cc < 8; ++cc) bb[cc] = g_bp[n0 + tx * 8 + cc];
    float rloc[12];
#pragma unroll
    for (int q = 0; q < 12; ++q) rloc[q] = 0.0f;

#pragma unroll
    for (int rr = 0; rr < 8; ++rr) {
        const int row = row0 + ty * 8 + rr, rl = ty * 8 + rr;
        const float guar = x[(size_t)row * XSTR + 128];
#pragma unroll
        for (int uu = 0; uu < 2; ++uu) {
            const int cb = uu * 4;
            const int ul = tx * 2 + uu, ug = ntile * 32 + ul;
            float i_g = sigmoidf_(acc[rr][cb + 0] + bb[cb + 0]);
            float f_g = sigmoidf_(acc[rr][cb + 1] + bb[cb + 1]);
            float ct  = tanhf_   (acc[rr][cb + 2] + bb[cb + 2]);
            float o_g = sigmoidf_(acc[rr][cb + 3] + bb[cb + 3]);
            float cv  = c[(size_t)row * 128 + ug];
            float cn  = f_g * cv + i_g * ct;
            float ht  = o_g * tanhf_(cn);

            out[(size_t)BSZ * 128 + (size_t)row * 128 + ug] = cn;

            float* gvp = &g_gv[(size_t)row * GVN + ug];
            gvp[0] = i_g; gvp[128] = f_g; gvp[256] = ct;
            gvp[384] = cn; gvp[512] = o_g; gvp[640] = ht;

            sT6[(0 * 32 + ul) * 130 + rl] = __float2bfloat16(i_g);
            sT6[(1 * 32 + ul) * 130 + rl] = __float2bfloat16(f_g);
            sT6[(2 * 32 + ul) * 130 + rl] = __float2bfloat16(ct);
            sT6[(3 * 32 + ul) * 130 + rl] = __float2bfloat16(cn);
            sT6[(4 * 32 + ul) * 130 + rl] = __float2bfloat16(o_g);
            sT6[(5 * 32 + ul) * 130 + rl] = __float2bfloat16(ht);

            rloc[0 * 2 + uu] += i_g * guar;  rloc[1 * 2 + uu] += f_g * guar;
            rloc[2 * 2 + uu] += ct  * guar;  rloc[3 * 2 + uu] += cn  * guar;
            rloc[4 * 2 + uu] += o_g * guar;  rloc[5 * 2 + uu] += ht  * guar;
        }
    }
#pragma unroll
    for (int blk = 0; blk < 6; ++blk)
#pragma unroll
        for (int uu = 0; uu < 2; ++uu)
            atomicAdd(&r_s[blk * 32 + tx * 2 + uu], rloc[blk * 2 + uu]);
    __syncthreads();
    if (tid < 192) {
        int blk = tid >> 5, ul = tid & 31;
        atomicAdd(&g_r[blk * 128 + ntile * 32 + ul], r_s[tid]);
    }
    for (int i = tid; i < 6 * 32 * 64; i += 256) {
        int g = i >> 11, rem = i & 2047, u = rem >> 6, ch = rem & 63;
        unsigned v = *reinterpret_cast<const unsigned*>(&sT6[(g * 32 + u) * 130 + ch * 2]);
        int j = g * 128 + ntile * 32 + u;
        reinterpret_cast<unsigned*>(&g_gvT[(size_t)j * BSZ + row0])[ch] = v;
    }
}

// ---------------- kernel 2: Gram via bf16 mma.sync ----------------
// grid (21, 16), 256 threads (8 warps, 2x4), double-buffered cp.async
__global__ __launch_bounds__(256) void gram_mma_kernel() {
    extern __shared__ char smraw[];
    const unsigned smb = smem_u32(smraw);
    const int tid = threadIdx.x;
    const int lane = tid & 31, wid = tid >> 5;
    const int wr = wid >> 2, wc = wid & 3;
    const int a = c_pa[blockIdx.x], bblk = c_pb[blockIdx.x];
    const int kbase = blockIdx.y * KPC;

    const __nv_bfloat16* baseA = g_gvT + (size_t)(a * 128) * BSZ;
    const __nv_bfloat16* baseB = g_gvT + (size_t)(bblk * 128) * BSZ;

    // loader: tile t -> buffer bf. layout: row j (128B = 8 chunks), chunk swizzled by j&7
    auto load_tile = [&](int t, int bf) {
        const int k0 = kbase + t * KC;
        const unsigned dbase = smb + bf * BUF_BYTES;
#pragma unroll
        for (int i = 0; i < 8; ++i) {
            int cidx = tid + 256 * i;
            int tile = cidx >> 10, j = (cidx >> 3) & 127, q = cidx & 7;
            const __nv_bfloat16* src = (tile ? baseB : baseA) + (size_t)j * BSZ + k0 + q * 8;
            unsigned off = (unsigned)(j * 128 + ((q ^ (j & 7)) << 4));
            cp_async16(dbase + tile * TILE_BYTES + off, src);
        }
        asm volatile("cp.async.commit_group;\n" ::: "memory");
    };

    // lane mappings for ldmatrix
    const int aRow = lane & 15;              // row within 16-row A tile
    const int aKg  = lane >> 4;              // k chunk 0/1
    const int bRow = ((lane >> 4) << 3) + (lane & 7);  // n within 16-row B tile
    const int bKg  = (lane >> 3) & 1;

    float acc[4][4][4];
#pragma unroll
    for (int i = 0; i < 4; ++i)
#pragma unroll
        for (int j = 0; j < 4; ++j)
#pragma unroll
            for (int q = 0; q < 4; ++q) acc[i][j][q] = 0.0f;

    load_tile(0, 0);
    for (int t = 0; t < GT; ++t) {
        if (t + 1 < GT) {
            load_tile(t + 1, (t + 1) & 1);
            asm volatile("cp.async.wait_group 1;\n" ::: "memory");
        } else {
            asm volatile("cp.async.wait_group 0;\n" ::: "memory");
        }
        __syncthreads();

        const unsigned sA = smb + (t & 1) * BUF_BYTES;
        const unsigned sB = sA + TILE_BYTES;
#pragma unroll
        for (int ks = 0; ks < 4; ++ks) {
            unsigned af[4][4];
#pragma unroll
            for (int i = 0; i < 4; ++i) {
                int row = wr * 64 + i * 16 + aRow;
                int cch = (ks * 2 + aKg) ^ (row & 7);
                ldsm_x4(sA + row * 128 + cch * 16, af[i][0], af[i][1], af[i][2], af[i][3]);
            }
            unsigned bf[4][2];
#pragma unroll
            for (int nc = 0; nc < 2; ++nc) {
                int row = wc * 32 + nc * 16 + bRow;
                int cch = (ks * 2 + bKg) ^ (row & 7);
                unsigned r0, r1, r2, r3;
                ldsm_x4(sB + row * 128 + cch * 16, r0, r1, r2, r3);
                bf[nc * 2 + 0][0] = r0; bf[nc * 2 + 0][1] = r1;
                bf[nc * 2 + 1][0] = r2; bf[nc * 2 + 1][1] = r3;
            }
#pragma unroll
            for (int i = 0; i < 4; ++i)
#pragma unroll
                for (int jn = 0; jn < 4; ++jn)
                    mma_bf16(acc[i][jn][0], acc[i][jn][1], acc[i][jn][2], acc[i][jn][3],
                             af[i][0], af[i][1], af[i][2], af[i][3],
                             bf[jn][0], bf[jn][1]);
        }
        __syncthreads();
    }

    // epilogue: store 128x128 fp32 partial (exclusive per CTA)
    float* dst = g_Gpart + ((size_t)blockIdx.x * KSPLIT + blockIdx.y) * 16384;
    const int r0 = lane >> 2, c0 = (lane & 3) * 2;
#pragma unroll
    for (int i = 0; i < 4; ++i) {
#pragma unroll
        for (int jn = 0; jn < 4; ++jn) {
            int row = wr * 64 + i * 16 + r0;
            int col = wc * 32 + jn * 8 + c0;
            float2 lo = make_float2(acc[i][jn][0], acc[i][jn][1]);
            float2 hi = make_float2(acc[i][jn][2], acc[i][jn][3]);
            *reinterpret_cast<float2*>(&dst[row * 128 + col]) = lo;
            *reinterpret_cast<float2*>(&dst[(row + 8) * 128 + col]) = hi;
        }
    }
}

__global__ __launch_bounds__(256) void greduce_kernel() {
    const int t = blockIdx.x * 256 + threadIdx.x;   // < 21*16384
    const int p = t >> 14, rem = t & 16383;
    const int m = rem >> 7, cc = rem & 127;
    float s = 0.0f;
#pragma unroll
    for (int ks = 0; ks < KSPLIT; ++ks)
        s += g_Gpart[(((size_t)p * KSPLIT + ks) << 14) + rem];
    const int a = c_pa[p], b = c_pb[p];
    g_G[(a * 128 + m) * GVN + b * 128 + cc] = s;
    if (a != b) g_G[(b * 128 + cc) * GVN + a * 128 + m] = s;
}

// grid 96, warp-per-row
__global__ __launch_bounds__(256) void gd_kernel(int flip) {
    const float* thin = flip ? g_thB : g_thA;
    float* thout = flip ? g_thA : g_thB;
    __shared__ float sth[GVN];
    const int tid = threadIdx.x;
    for (int i = tid; i < GVN; i += 256) sth[i] = thin[i];
    __syncthreads();
    const int warp = tid >> 5, lane = tid & 31;
    const int j = blockIdx.x * 8 + warp;
    const float4* Grow = reinterpret_cast<const float4*>(&g_G[(size_t)j * GVN]);
    const float4* st4 = reinterpret_cast<const float4*>(sth);
    float s = 0.0f;
#pragma unroll
    for (int t = 0; t < 6; ++t) {
        int q = lane + 32 * t;
        float4 g4 = Grow[q], t4 = st4[q];
        s = fmaf(g4.x, t4.x, s); s = fmaf(g4.y, t4.y, s);
        s = fmaf(g4.z, t4.z, s); s = fmaf(g4.w, t4.w, s);
    }
#pragma unroll
    for (int o = 16; o; o >>= 1) s += __shfl_xor_sync(0xffffffffu, s, o);
    if (lane == 0)
        thout[j] = sth[j] - 0.0001f * (2.0f / 65536.0f) * (s - g_r[j]);
}

__global__ void argmax_kernel() {
    __shared__ float simp[6];
    if (threadIdx.x < 6) simp[threadIdx.x] = 0.0f;
    __syncthreads();
    for (int i = threadIdx.x; i < GVN; i += 256)
        atomicAdd(&simp[i >> 7], fabsf(g_thB[i]));
    __syncthreads();
    if (threadIdx.x == 0) {
        int best = 0; float bv = simp[0];
#pragma unroll
        for (int k = 1; k < 6; ++k)
            if (simp[k] > bv) { bv = simp[k]; best = k; }
        g_maxidx = best;
    }
}

__global__ __launch_bounds__(256) void gather_kernel(float* __restrict__ out) {
    const int t = blockIdx.x * blockDim.x + threadIdx.x;
    const int mi = g_maxidx;
    const int e = t * 4, row = e >> 7, jj = e & 127;
    float4 v = *reinterpret_cast<const float4*>(&g_gv[(size_t)row * GVN + mi * 128 + jj]);
    *reinterpret_cast<float4*>(&out[e]) = v;
}

extern "C" void kernel_launch(void* const* d_in, const int* in_sizes, int n_in,
                              void* d_out, int out_size) {
    (void)in_sizes; (void)n_in; (void)out_size;
    const float* x    = (const float*)d_in[0];
    const float* h    = (const float*)d_in[1];
    const float* c    = (const float*)d_in[2];
    const float* W_ih = (const float*)d_in[3];
    const float* b_ih = (const float*)d_in[4];
    const float* W_hh = (const float*)d_in[5];
    float* out = (float*)d_out;

    cudaFuncSetAttribute(lstm_kernel,
                         cudaFuncAttributeMaxDynamicSharedMemorySize, LSTM_SMEM);
    cudaFuncSetAttribute(gram_mma_kernel,
                         cudaFuncAttributeMaxDynamicSharedMemorySize, GRAM_SMEM);

    const int prepN = GVN + GVN + ZN + 256 * 512;
    prep_kernel<<<(prepN + 255) / 256, 256>>>(W_ih, W_hh, b_ih);

    dim3 g1(4, BSZ / 128);
    lstm_kernel<<<g1, 256, LSTM_SMEM>>>(x, h, c, out);

    dim3 g2(NPAIR, KSPLIT);
    gram_mma_kernel<<<g2, 256, GRAM_SMEM>>>();

    greduce_kernel<<<(NPAIR * 16384) / 256, 256>>>();

    for (int k = 0; k < 13; ++k)
        gd_kernel<<<96, 256>>>(k & 1);

    argmax_kernel<<<1, 256>>>();
    gather_kernel<<<(BSZ * 128 / 4) / 256, 256>>>(out);
}

// round 12
// speedup vs baseline: 1.0004x; 1.0004x over previous
#include <cuda_runtime.h>
#include <cuda_bf16.h>
#include <math.h>
#include <stdint.h>

#define BSZ   65536
#define ZN    512
#define GVN   768
#define XSTR  129
#define NPAIR 21
#define KSPLIT 16
#define KPC   (BSZ / KSPLIT)       // 4096
#define KC    64
#define GT    (KPC / KC)           // 64
#define TILE_BYTES (128 * KC * 2)  // 16384 bytes per operand tile
#define BUF_BYTES  (2 * TILE_BYTES)
#define GRAM_SMEM  (2 * BUF_BYTES) // 65536
#define LSTM_SMEM  83968

__device__ float g_Wp[256 * 512];
__device__ float g_bp[512];
__device__ float g_gv[(size_t)BSZ * GVN];
__device__ __nv_bfloat16 g_gvT[(size_t)GVN * BSZ];
__device__ float g_Gpart[(size_t)NPAIR * KSPLIT * 128 * 128];
__device__ float g_G[GVN * GVN];
__device__ float g_r[GVN];
__device__ float g_thA[GVN];
__device__ float g_thB[GVN];
__device__ int   g_maxidx;

__constant__ int c_pa[NPAIR] = {0,0,0,0,0,0,1,1,1,1,1,2,2,2,2,3,3,3,4,4,5};
__constant__ int c_pb[NPAIR] = {0,1,2,3,4,5,1,2,3,4,5,2,3,4,5,3,4,5,4,5,5};

__device__ __forceinline__ unsigned smem_u32(const void* p) {
    unsigned a;
    asm("{ .reg .u64 t; cvta.to.shared.u64 t, %1; cvt.u32.u64 %0, t; }" : "=r"(a) : "l"(p));
    return a;
}
__device__ __forceinline__ void cp_async16(unsigned dst, const void* src) {
    asm volatile("cp.async.cg.shared.global [%0], [%1], 16;\n" :: "r"(dst), "l"(src));
}
__device__ __forceinline__ void ldsm_x4(unsigned addr, unsigned& r0, unsigned& r1,
                                        unsigned& r2, unsigned& r3) {
    asm volatile("ldmatrix.sync.aligned.m8n8.x4.shared.b16 {%0,%1,%2,%3}, [%4];"
                 : "=r"(r0), "=r"(r1), "=r"(r2), "=r"(r3) : "r"(addr));
}
__device__ __forceinline__ void mma_bf16(float& c0, float& c1, float& c2, float& c3,
                                         unsigned a0, unsigned a1, unsigned a2, unsigned a3,
                                         unsigned b0, unsigned b1) {
    asm volatile(
        "mma.sync.aligned.m16n8k16.row.col.f32.bf16.bf16.f32 "
        "{%0,%1,%2,%3}, {%4,%5,%6,%7}, {%8,%9}, {%0,%1,%2,%3};"
        : "+f"(c0), "+f"(c1), "+f"(c2), "+f"(c3)
        : "r"(a0), "r"(a1), "r"(a2), "r"(a3), "r"(b0), "r"(b1));
}

__device__ __forceinline__ float sigmoidf_(float x) { return 1.0f / (1.0f + __expf(-x)); }
__device__ __forceinline__ float tanhf_(float x) {
    float t = __expf(-2.0f * fabsf(x));
    return copysignf((1.0f - t) / (1.0f + t), x);
}

__global__ void prep_kernel(const float* __restrict__ W_ih,
                            const float* __restrict__ W_hh,
                            const float* __restrict__ b_ih) {
    int t = blockIdx.x * blockDim.x + threadIdx.x;
    if (t < GVN) { g_r[t] = 0.0f; return; }
    t -= GVN;
    if (t < GVN) { g_thA[t] = 1.0f; return; }
    t -= GVN;
    if (t < ZN) { int j = t >> 2, g = t & 3; g_bp[t] = b_ih[g * 128 + j]; return; }
    t -= ZN;
    if (t < 256 * 512) {
        int k = t >> 9, cp = t & 511;
        int j = cp >> 2, g = cp & 3, wr = g * 128 + j;
        g_Wp[t] = (k < 128) ? W_ih[wr * 128 + k] : W_hh[wr * 128 + (k - 128)];
    }
}

// ---------------- kernel 1: z-GEMM + gates + bf16 transposed staging ----------------
__global__ __launch_bounds__(256) void lstm_kernel(
        const float* __restrict__ x, const float* __restrict__ h,
        const float* __restrict__ c, float* __restrict__ out) {
    extern __shared__ char smraw[];
    float* As  = (float*)(smraw);
    float* Bs  = (float*)(smraw + 16896);
    float* r_s = (float*)(smraw + 33280);
    __nv_bfloat16* sT6 = (__nv_bfloat16*)(smraw + 34048);  // [6][32][130]

    const int tid = threadIdx.x, ntile = blockIdx.x;
    const int row0 = blockIdx.y * 128, n0 = ntile * 128;
    const int kkL = tid & 31, m0 = tid >> 5;
    const int nL = tid & 127, kk0 = tid >> 7;
    const int ty = tid >> 4, tx = tid & 15;

    float acc[8][8];
#pragma unroll
    for (int i = 0; i < 8; ++i)
#pragma unroll
        for (int j = 0; j < 8; ++j) acc[i][j] = 0.0f;

    for (int kt = 0; kt < 8; ++kt) {
        const int k0 = kt * 32;
        const float* src; int stride, koff;
        if (k0 < 128) { src = x; stride = XSTR; koff = k0; }
        else          { src = h; stride = 128;  koff = k0 - 128; }
#pragma unroll
        for (int i = 0; i < 16; ++i) {
            int m = m0 + 8 * i;
            As[kkL * 132 + m] = src[(size_t)(row0 + m) * stride + koff + kkL];
        }
#pragma unroll
        for (int i = 0; i < 16; ++i) {
            int kk = kk0 + 2 * i;
            Bs[kk * 128 + nL] = g_Wp[(k0 + kk) * 512 + n0 + nL];
        }
        __syncthreads();
#pragma unroll
        for (int kk = 0; kk < 32; ++kk) {
            float4 a0 = *reinterpret_cast<const float4*>(&As[kk * 132 + ty * 8]);
            float4 a1 = *reinterpret_cast<const float4*>(&As[kk * 132 + ty * 8 + 4]);
            float4 b0 = *reinterpret_cast<const float4*>(&Bs[kk * 128 + tx * 8]);
            float4 b1 = *reinterpret_cast<const float4*>(&Bs[kk * 128 + tx * 8 + 4]);
            float av[8] = {a0.x, a0.y, a0.z, a0.w, a1.x, a1.y, a1.z, a1.w};
            float bv[8] = {b0.x, b0.y, b0.z, b0.w, b1.x, b1.y, b1.z, b1.w};
#pragma unroll
            for (int i = 0; i < 8; ++i)
#pragma unroll
                for (int j = 0; j < 8; ++j)
                    acc[i][j] = fmaf(av[i], bv[j], acc[i][j]);
        }
        __syncthreads();
    }

    if (tid < 192) r_s[tid] = 0.0f;
    __syncthreads();

    float bb[8];
#pragma unroll
    for (int cc = 0; cc < 8; ++cc) bb[cc] = g_bp[n0 + tx * 8 + cc];
    float rloc[12];
#pragma unroll
    for (int q = 0; q < 12; ++q) rloc[q] = 0.0f;

#pragma unroll
    for (int rr = 0; rr < 8; ++rr) {
        const int row = row0 + ty * 8 + rr, rl = ty * 8 + rr;
        const float guar = x[(size_t)row * XSTR + 128];
#pragma unroll
        for (int uu = 0; uu < 2; ++uu) {
            const int cb = uu * 4;
            const int ul = tx * 2 + uu, ug = ntile * 32 + ul;
            float i_g = sigmoidf_(acc[rr][cb + 0] + bb[cb + 0]);
            float f_g = sigmoidf_(acc[rr][cb + 1] + bb[cb + 1]);
            float ct  = tanhf_   (acc[rr][cb + 2] + bb[cb + 2]);
            float o_g = sigmoidf_(acc[rr][cb + 3] + bb[cb + 3]);
            float cv  = c[(size_t)row * 128 + ug];
            float cn  = f_g * cv + i_g * ct;
            float ht  = o_g * tanhf_(cn);

            out[(size_t)BSZ * 128 + (size_t)row * 128 + ug] = cn;

            float* gvp = &g_gv[(size_t)row * GVN + ug];
            gvp[0] = i_g; gvp[128] = f_g; gvp[256] = ct;
            gvp[384] = cn; gvp[512] = o_g; gvp[640] = ht;

            sT6[(0 * 32 + ul) * 130 + rl] = __float2bfloat16(i_g);
            sT6[(1 * 32 + ul) * 130 + rl] = __float2bfloat16(f_g);
            sT6[(2 * 32 + ul) * 130 + rl] = __float2bfloat16(ct);
            sT6[(3 * 32 + ul) * 130 + rl] = __float2bfloat16(cn);
            sT6[(4 * 32 + ul) * 130 + rl] = __float2bfloat16(o_g);
            sT6[(5 * 32 + ul) * 130 + rl] = __float2bfloat16(ht);

            rloc[0 * 2 + uu] += i_g * guar;  rloc[1 * 2 + uu] += f_g * guar;
            rloc[2 * 2 + uu] += ct  * guar;  rloc[3 * 2 + uu] += cn  * guar;
            rloc[4 * 2 + uu] += o_g * guar;  rloc[5 * 2 + uu] += ht  * guar;
        }
    }
#pragma unroll
    for (int blk = 0; blk < 6; ++blk)
#pragma unroll
        for (int uu = 0; uu < 2; ++uu)
            atomicAdd(&r_s[blk * 32 + tx * 2 + uu], rloc[blk * 2 + uu]);
    __syncthreads();
    if (tid < 192) {
        int blk = tid >> 5, ul = tid & 31;
        atomicAdd(&g_r[blk * 128 + ntile * 32 + ul], r_s[tid]);
    }
    for (int i = tid; i < 6 * 32 * 64; i += 256) {
        int g = i >> 11, rem = i & 2047, u = rem >> 6, ch = rem & 63;
        unsigned v = *reinterpret_cast<const unsigned*>(&sT6[(g * 32 + u) * 130 + ch * 2]);
        int j = g * 128 + ntile * 32 + u;
        reinterpret_cast<unsigned*>(&g_gvT[(size_t)j * BSZ + row0])[ch] = v;
    }
}

// ---------------- kernel 2: Gram via bf16 mma.sync ----------------
// grid (21, 16), 256 threads (8 warps, 2x4), double-buffered cp.async
__global__ __launch_bounds__(256) void gram_mma_kernel() {
    extern __shared__ char smraw[];
    const unsigned smb = smem_u32(smraw);
    const int tid = threadIdx.x;
    const int lane = tid & 31, wid = tid >> 5;
    const int wr = wid >> 2, wc = wid & 3;
    const int a = c_pa[blockIdx.x], bblk = c_pb[blockIdx.x];
    const int kbase = blockIdx.y * KPC;

    const __nv_bfloat16* baseA = g_gvT + (size_t)(a * 128) * BSZ;
    const __nv_bfloat16* baseB = g_gvT + (size_t)(bblk * 128) * BSZ;

    // loader: tile t -> buffer bf. layout: row j (128B = 8 chunks), chunk swizzled by j&7
    auto load_tile = [&](int t, int bf) {
        const int k0 = kbase + t * KC;
        const unsigned dbase = smb + bf * BUF_BYTES;
#pragma unroll
        for (int i = 0; i < 8; ++i) {
            int cidx = tid + 256 * i;
            int tile = cidx >> 10, j = (cidx >> 3) & 127, q = cidx & 7;
            const __nv_bfloat16* src = (tile ? baseB : baseA) + (size_t)j * BSZ + k0 + q * 8;
            unsigned off = (unsigned)(j * 128 + ((q ^ (j & 7)) << 4));
            cp_async16(dbase + tile * TILE_BYTES + off, src);
        }
        asm volatile("cp.async.commit_group;\n" ::: "memory");
    };

    // lane mappings for ldmatrix
    const int aRow = lane & 15;              // row within 16-row A tile
    const int aKg  = lane >> 4;              // k chunk 0/1
    const int bRow = ((lane >> 4) << 3) + (lane & 7);  // n within 16-row B tile
    const int bKg  = (lane >> 3) & 1;

    float acc[4][4][4];
#pragma unroll
    for (int i = 0; i < 4; ++i)
#pragma unroll
        for (int j = 0; j < 4; ++j)
#pragma unroll
            for (int q = 0; q < 4; ++q) acc[i][j][q] = 0.0f;

    load_tile(0, 0);
    for (int t = 0; t < GT; ++t) {
        if (t + 1 < GT) {
            load_tile(t + 1, (t + 1) & 1);
            asm volatile("cp.async.wait_group 1;\n" ::: "memory");
        } else {
            asm volatile("cp.async.wait_group 0;\n" ::: "memory");
        }
        __syncthreads();

        const unsigned sA = smb + (t & 1) * BUF_BYTES;
        const unsigned sB = sA + TILE_BYTES;
#pragma unroll
        for (int ks = 0; ks < 4; ++ks) {
            unsigned af[4][4];
#pragma unroll
            for (int i = 0; i < 4; ++i) {
                int row = wr * 64 + i * 16 + aRow;
                int cch = (ks * 2 + aKg) ^ (row & 7);
                ldsm_x4(sA + row * 128 + cch * 16, af[i][0], af[i][1], af[i][2], af[i][3]);
            }
            unsigned bf[4][2];
#pragma unroll
            for (int nc = 0; nc < 2; ++nc) {
                int row = wc * 32 + nc * 16 + bRow;
                int cch = (ks * 2 + bKg) ^ (row & 7);
                unsigned r0, r1, r2, r3;
                ldsm_x4(sB + row * 128 + cch * 16, r0, r1, r2, r3);
                bf[nc * 2 + 0][0] = r0; bf[nc * 2 + 0][1] = r1;
                bf[nc * 2 + 1][0] = r2; bf[nc * 2 + 1][1] = r3;
            }
#pragma unroll
            for (int i = 0; i < 4; ++i)
#pragma unroll
                for (int jn = 0; jn < 4; ++jn)
                    mma_bf16(acc[i][jn][0], acc[i][jn][1], acc[i][jn][2], acc[i][jn][3],
                             af[i][0], af[i][1], af[i][2], af[i][3],
                             bf[jn][0], bf[jn][1]);
        }
        __syncthreads();
    }

    // epilogue: store 128x128 fp32 partial (exclusive per CTA)
    float* dst = g_Gpart + ((size_t)blockIdx.x * KSPLIT + blockIdx.y) * 16384;
    const int r0 = lane >> 2, c0 = (lane & 3) * 2;
#pragma unroll
    for (int i = 0; i < 4; ++i) {
#pragma unroll
        for (int jn = 0; jn < 4; ++jn) {
            int row = wr * 64 + i * 16 + r0;
            int col = wc * 32 + jn * 8 + c0;
            float2 lo = make_float2(acc[i][jn][0], acc[i][jn][1]);
            float2 hi = make_float2(acc[i][jn][2], acc[i][jn][3]);
            *reinterpret_cast<float2*>(&dst[row * 128 + col]) = lo;
            *reinterpret_cast<float2*>(&dst[(row + 8) * 128 + col]) = hi;
        }
    }
}

__global__ __launch_bounds__(256) void greduce_kernel() {
    const int t = blockIdx.x * 256 + threadIdx.x;   // < 21*16384
    const int p = t >> 14, rem = t & 16383;
    const int m = rem >> 7, cc = rem & 127;
    float s = 0.0f;
#pragma unroll
    for (int ks = 0; ks < KSPLIT; ++ks)
        s += g_Gpart[(((size_t)p * KSPLIT + ks) << 14) + rem];
    const int a = c_pa[p], b = c_pb[p];
    g_G[(a * 128 + m) * GVN + b * 128 + cc] = s;
    if (a != b) g_G[(b * 128 + cc) * GVN + a * 128 + m] = s;
}

// grid 96, warp-per-row
__global__ __launch_bounds__(256) void gd_kernel(int flip) {
    const float* thin = flip ? g_thB : g_thA;
    float* thout = flip ? g_thA : g_thB;
    __shared__ float sth[GVN];
    const int tid = threadIdx.x;
    for (int i = tid; i < GVN; i += 256) sth[i] = thin[i];
    __syncthreads();
    const int warp = tid >> 5, lane = tid & 31;
    const int j = blockIdx.x * 8 + warp;
    const float4* Grow = reinterpret_cast<const float4*>(&g_G[(size_t)j * GVN]);
    const float4* st4 = reinterpret_cast<const float4*>(sth);
    float s = 0.0f;
#pragma unroll
    for (int t = 0; t < 6; ++t) {
        int q = lane + 32 * t;
        float4 g4 = Grow[q], t4 = st4[q];
        s = fmaf(g4.x, t4.x, s); s = fmaf(g4.y, t4.y, s);
        s = fmaf(g4.z, t4.z, s); s = fmaf(g4.w, t4.w, s);
    }
#pragma unroll
    for (int o = 16; o; o >>= 1) s += __shfl_xor_sync(0xffffffffu, s, o);
    if (lane == 0)
        thout[j] = sth[j] - 0.0001f * (2.0f / 65536.0f) * (s - g_r[j]);
}

__global__ void argmax_kernel() {
    __shared__ float simp[6];
    if (threadIdx.x < 6) simp[threadIdx.x] = 0.0f;
    __syncthreads();
    for (int i = threadIdx.x; i < GVN; i += 256)
        atomicAdd(&simp[i >> 7], fabsf(g_thB[i]));
    __syncthreads();
    if (threadIdx.x == 0) {
        int best = 0; float bv = simp[0];
#pragma unroll
        for (int k = 1; k < 6; ++k)
            if (simp[k] > bv) { bv = simp[k]; best = k; }
        g_maxidx = best;
    }
}

__global__ __launch_bounds__(256) void gather_kernel(float* __restrict__ out) {
    const int t = blockIdx.x * blockDim.x + threadIdx.x;
    const int mi = g_maxidx;
    const int e = t * 4, row = e >> 7, jj = e & 127;
    float4 v = *reinterpret_cast<const float4*>(&g_gv[(size_t)row * GVN + mi * 128 + jj]);
    *reinterpret_cast<float4*>(&out[e]) = v;
}

extern "C" void kernel_launch(void* const* d_in, const int* in_sizes, int n_in,
                              void* d_out, int out_size) {
    (void)in_sizes; (void)n_in; (void)out_size;
    const float* x    = (const float*)d_in[0];
    const float* h    = (const float*)d_in[1];
    const float* c    = (const float*)d_in[2];
    const float* W_ih = (const float*)d_in[3];
    const float* b_ih = (const float*)d_in[4];
    const float* W_hh = (const float*)d_in[5];
    float* out = (float*)d_out;

    cudaFuncSetAttribute(lstm_kernel,
                         cudaFuncAttributeMaxDynamicSharedMemorySize, LSTM_SMEM);
    cudaFuncSetAttribute(gram_mma_kernel,
                         cudaFuncAttributeMaxDynamicSharedMemorySize, GRAM_SMEM);

    const int prepN = GVN + GVN + ZN + 256 * 512;
    prep_kernel<<<(prepN + 255) / 256, 256>>>(W_ih, W_hh, b_ih);

    dim3 g1(4, BSZ / 128);
    lstm_kernel<<<g1, 256, LSTM_SMEM>>>(x, h, c, out);

    dim3 g2(NPAIR, KSPLIT);
    gram_mma_kernel<<<g2, 256, GRAM_SMEM>>>();

    greduce_kernel<<<(NPAIR * 16384) / 256, 256>>>();

    for (int k = 0; k < 13; ++k)
        gd_kernel<<<96, 256>>>(k & 1);

    argmax_kernel<<<1, 256>>>();
    gather_kernel<<<(BSZ * 128 / 4) / 256, 256>>>(out);
}